// round 1
// baseline (speedup 1.0000x reference)
#include <cuda_runtime.h>

// FlexGroupedVarPatchEmbed: out[b,v,l,e] = sum_{p,q} x[b,v,hh*8+p,ww*8+q] * W[vars[v],e,p,q] + bias[vars[v],e]
// B=2 V=16 H=W=512 P=8 -> per-v GEMM M=8192 N=1024 K=64, fp32.
// Tile: M=128 (2 patch rows), N=128, K=64 (one shot). f32x2 packed FFMA for 2x fp32 rate.

#define NTHREADS 256

__device__ __forceinline__ unsigned long long ffma2(unsigned long long a,
                                                    unsigned long long b,
                                                    unsigned long long c) {
    unsigned long long d;
    asm("fma.rn.f32x2 %0, %1, %2, %3;" : "=l"(d) : "l"(a), "l"(b), "l"(c));
    return d;
}
__device__ __forceinline__ unsigned long long splat2(float x) {
    unsigned long long d;
    asm("mov.b64 %0, {%1, %1};" : "=l"(d) : "f"(x));
    return d;
}
__device__ __forceinline__ float2 unpack2(unsigned long long v) {
    float2 r;
    asm("mov.b64 {%0, %1}, %2;" : "=f"(r.x), "=f"(r.y) : "l"(v));
    return r;
}

__global__ __launch_bounds__(NTHREADS, 2)
void patch_embed_kernel(const float* __restrict__ x,
                        const int* __restrict__ vars,
                        const float* __restrict__ pw,
                        const float* __restrict__ pb,
                        float* __restrict__ out) {
    extern __shared__ float smem[];
    float* As = smem;            // [64 k][128 m]  k-major
    float* Bs = smem + 64 * 128; // [64 k][128 n]  k-major

    const int tid = threadIdx.x;
    const int e0  = blockIdx.x << 7;  // 128-wide E tile
    const int hp  = blockIdx.y;       // patch-row pair: hh0 = hp*2
    const int bv  = blockIdx.z;       // b*16 + v
    const int v   = bv & 15;
    const int var = vars[v];

    const float* xbase = x  + (size_t)bv  * (512u * 512u) + (size_t)hp * (16u * 512u);
    const float* wbase = pw + (size_t)var * (1024u * 64u) + (size_t)e0 * 64u;

    // ---- Load A tile: 16 contiguous rows of x (512 floats each) ----
    // A[k = p*8+q][m = hh_local*64 + ww] = x[row = hh_local*8+p][col = ww*8+q]
    #pragma unroll
    for (int i = 0; i < 8; i++) {
        int idx4 = tid + i * 256;          // float4 index, 2048 total
        int r    = idx4 >> 7;              // 0..15
        int c0   = (idx4 & 127) << 2;      // 0..508, multiple of 4
        float4 val = *(const float4*)(xbase + r * 512 + c0);
        int m  = ((r >> 3) << 6) + (c0 >> 3);
        int k0 = ((r & 7) << 3) + (c0 & 7);   // q0 in {0,4}: 4 consecutive k, same m
        As[(k0 + 0) * 128 + m] = val.x;
        As[(k0 + 1) * 128 + m] = val.y;
        As[(k0 + 2) * 128 + m] = val.z;
        As[(k0 + 3) * 128 + m] = val.w;
    }

    // ---- Load B tile: 128 weight rows of 64 floats ----
    // thread map: n fastest across threads -> conflict-free STS (banks consecutive)
    #pragma unroll
    for (int i = 0; i < 8; i++) {
        int idx4 = tid + i * 256;
        int n    = idx4 & 127;
        int k0   = (idx4 >> 7) << 2;       // 0,4,...,60
        float4 val = *(const float4*)(wbase + n * 64 + k0);
        Bs[(k0 + 0) * 128 + n] = val.x;
        Bs[(k0 + 1) * 128 + n] = val.y;
        Bs[(k0 + 2) * 128 + n] = val.z;
        Bs[(k0 + 3) * 128 + n] = val.w;
    }
    __syncthreads();

    // ---- Compute: per-thread 8m x 8n, f32x2 pairs along m ----
    const int tx = tid & 15;     // n lane: n = tx + 16*jn (interleaved -> conflict-free B reads)
    const int ty = tid >> 4;     // m block: m0 = ty*8
    const int m0 = ty << 3;

    unsigned long long acc[8][4];
    #pragma unroll
    for (int jn = 0; jn < 8; jn++)
        #pragma unroll
        for (int mj = 0; mj < 4; mj++)
            acc[jn][mj] = 0ull;

    #pragma unroll 8
    for (int k = 0; k < 64; k++) {
        unsigned long long a2[4];
        #pragma unroll
        for (int mj = 0; mj < 4; mj++)
            a2[mj] = *(const unsigned long long*)(As + k * 128 + m0 + 2 * mj);
        #pragma unroll
        for (int jn = 0; jn < 8; jn++) {
            unsigned long long b2 = splat2(Bs[k * 128 + tx + 16 * jn]);
            #pragma unroll
            for (int mj = 0; mj < 4; mj++)
                acc[jn][mj] = ffma2(a2[mj], b2, acc[jn][mj]);
        }
    }

    // ---- Epilogue: bias + store ----
    const float* bias = pb + (size_t)var * 1024u + e0;
    float bvals[8];
    #pragma unroll
    for (int jn = 0; jn < 8; jn++)
        bvals[jn] = bias[tx + 16 * jn];

    // l = hh0*64 + m = hp*128 + m  (contiguous within tile)
    float* obase = out + ((size_t)bv * 4096u + (size_t)hp * 128u) * 1024u + e0;
    #pragma unroll
    for (int mj = 0; mj < 4; mj++) {
        float* orow0 = obase + (size_t)(m0 + 2 * mj) * 1024u;
        float* orow1 = orow0 + 1024u;
        #pragma unroll
        for (int jn = 0; jn < 8; jn++) {
            float2 p = unpack2(acc[jn][mj]);
            orow0[tx + 16 * jn] = p.x + bvals[jn];
            orow1[tx + 16 * jn] = p.y + bvals[jn];
        }
    }
}

extern "C" void kernel_launch(void* const* d_in, const int* in_sizes, int n_in,
                              void* d_out, int out_size) {
    const float* x    = (const float*)d_in[0];
    const int*   vars = (const int*)d_in[1];
    const float* pw   = (const float*)d_in[2];
    const float* pb   = (const float*)d_in[3];
    float*       out  = (float*)d_out;

    const int smem_bytes = 2 * 64 * 128 * sizeof(float); // 64 KB
    cudaFuncSetAttribute(patch_embed_kernel,
                         cudaFuncAttributeMaxDynamicSharedMemorySize, smem_bytes);

    dim3 grid(8 /*E tiles*/, 32 /*patch-row pairs*/, 32 /*b*v*/);
    patch_embed_kernel<<<grid, NTHREADS, smem_bytes>>>(x, vars, pw, pb, out);
}

// round 6
// speedup vs baseline: 2.2345x; 2.2345x over previous
#include <cuda_runtime.h>
#include <cstdint>

// FlexGroupedVarPatchEmbed via mma.sync bf16 split-GEMM (portable PTX: no tcgen05,
// the harness compiles for plain sm_103 which rejects 'a'-only features).
// out[b,v,l,e] = sum_k x_patch[m,k] * W[var,e,k] + bias[var,e]
// Block: M=128 (2 patch rows), N=128 (E tile), K=64, fp32 via bf16 hi/lo split:
//   D = Ah*Bh + Ah*Bl + Al*Bh     (Al*Bl dropped, ~2^-18 relative)

#define NTHREADS 256

__device__ __forceinline__ uint32_t smem_u32(const void* p) {
    uint32_t a;
    asm("{ .reg .u64 t; cvta.to.shared.u64 t, %1; cvt.u32.u64 %0, t; }" : "=r"(a) : "l"(p));
    return a;
}
__device__ __forceinline__ uint32_t sw128(uint32_t off) { return off ^ ((off >> 3) & 0x70); }

// returns packed word: low half = bf16(lo), high half = bf16(hi)
__device__ __forceinline__ uint32_t pack_bf16x2(float lo, float hi) {
    uint32_t r;
    asm("cvt.rn.bf16x2.f32 %0, %1, %2;" : "=r"(r) : "f"(hi), "f"(lo));
    return r;
}
__device__ __forceinline__ float bfl(uint32_t w) { return __uint_as_float(w << 16); }
__device__ __forceinline__ float bfh(uint32_t w) { return __uint_as_float(w & 0xffff0000u); }

__device__ __forceinline__ void ldmx4(uint32_t* f, uint32_t addr) {
    asm volatile("ldmatrix.sync.aligned.m8n8.x4.shared.b16 {%0,%1,%2,%3}, [%4];"
                 : "=r"(f[0]), "=r"(f[1]), "=r"(f[2]), "=r"(f[3]) : "r"(addr));
}
__device__ __forceinline__ void mma16816(float* c, const uint32_t* a, uint32_t b0, uint32_t b1) {
    asm volatile(
        "mma.sync.aligned.m16n8k16.row.col.f32.bf16.bf16.f32 "
        "{%0,%1,%2,%3}, {%4,%5,%6,%7}, {%8,%9}, {%0,%1,%2,%3};"
        : "+f"(c[0]), "+f"(c[1]), "+f"(c[2]), "+f"(c[3])
        : "r"(a[0]), "r"(a[1]), "r"(a[2]), "r"(a[3]), "r"(b0), "r"(b1));
}

// smem byte offsets (tiles 1024-aligned for SW128 pattern)
#define OFF_BIAS  0                    // 128 floats
#define OFF_AH    1024                 // 128m x 64k bf16, 16KB
#define OFF_AL    (OFF_AH + 16384)
#define OFF_BH    (OFF_AL + 16384)     // 128n x 64k bf16, 16KB
#define OFF_BL    (OFF_BH + 16384)
#define SMEM_SZ   (OFF_BL + 16384)     // 66560 B

__global__ __launch_bounds__(NTHREADS, 2)
void patch_embed_mma(const float* __restrict__ x,
                     const int* __restrict__ vars,
                     const float* __restrict__ pw,
                     const float* __restrict__ pb,
                     float* __restrict__ out) {
    extern __shared__ char smem[];
    const uint32_t sb = smem_u32(smem);
    const int tid  = threadIdx.x;
    const int lane = tid & 31;
    const int wid  = tid >> 5;

    const int e0 = blockIdx.x << 7;    // 128-wide E tile
    const int hp = blockIdx.y;         // patch-row pair: hh0 = hp*2
    const int bv = blockIdx.z;         // b*16 + v
    const int v  = bv & 15;
    const int var = vars[v];

    const float* xbase = x  + (size_t)bv * (512u * 512u) + (size_t)hp * (16u * 512u);
    const float* wbase = pw + (size_t)var * (1024u * 64u) + (size_t)e0 * 64u;

    // ---- A tile: 16 contiguous x rows -> bf16 hi/lo, K-major [m][k], SW128 ----
    // A[k=p*8+q][m=hh_local*64+ww] = x[row=hh_local*8+p][col=ww*8+q]
    #pragma unroll
    for (int i = 0; i < 8; i++) {
        int idx4 = tid + i * 256;            // 2048 float4 total
        int r    = idx4 >> 7;                // 0..15
        int c0   = (idx4 & 127) << 2;        // multiple of 4
        float4 val = *(const float4*)(xbase + r * 512 + c0);
        int m  = ((r >> 3) << 6) + (c0 >> 3);
        int k0 = ((r & 7) << 3) + (c0 & 7);  // multiple of 4
        uint32_t h0 = pack_bf16x2(val.x, val.y);
        uint32_t h1 = pack_bf16x2(val.z, val.w);
        uint32_t l0 = pack_bf16x2(val.x - bfl(h0), val.y - bfh(h0));
        uint32_t l1 = pack_bf16x2(val.z - bfl(h1), val.w - bfh(h1));
        uint32_t boff = sw128((uint32_t)(m * 128 + k0 * 2));   // 8B aligned
        *(uint2*)(smem + OFF_AH + boff) = make_uint2(h0, h1);
        *(uint2*)(smem + OFF_AL + boff) = make_uint2(l0, l1);
    }

    // ---- B tile: 128 weight rows of 64 -> bf16 hi/lo, K-major [n][k], SW128 ----
    #pragma unroll
    for (int i = 0; i < 8; i++) {
        int idx4 = tid + i * 256;
        int n  = idx4 >> 4;
        int k0 = (idx4 & 15) << 2;
        float4 val = *(const float4*)(wbase + n * 64 + k0);
        uint32_t h0 = pack_bf16x2(val.x, val.y);
        uint32_t h1 = pack_bf16x2(val.z, val.w);
        uint32_t l0 = pack_bf16x2(val.x - bfl(h0), val.y - bfh(h0));
        uint32_t l1 = pack_bf16x2(val.z - bfl(h1), val.w - bfh(h1));
        uint32_t boff = sw128((uint32_t)(n * 128 + k0 * 2));
        *(uint2*)(smem + OFF_BH + boff) = make_uint2(h0, h1);
        *(uint2*)(smem + OFF_BL + boff) = make_uint2(l0, l1);
    }

    // bias tile
    if (tid < 128)
        ((float*)(smem + OFF_BIAS))[tid] = pb[(size_t)var * 1024u + e0 + tid];

    __syncthreads();

    // ---- Compute: 8 warps in 2(m) x 4(n); warp tile m64 x n32 ----
    const int wm = (wid & 1) << 6;     // 0 or 64
    const int wn = (wid >> 1) << 5;    // 0,32,64,96

    float acc[4][4][4];
    #pragma unroll
    for (int mt = 0; mt < 4; mt++)
        #pragma unroll
        for (int nt = 0; nt < 4; nt++)
            #pragma unroll
            for (int j = 0; j < 4; j++) acc[mt][nt][j] = 0.f;

    // ldmatrix lane addressing
    // A m16k16 frag: lanes 0-15 rows m+0..15 @k0; lanes 16-31 same rows @k+8
    const uint32_t a_row = wm + (lane & 15);
    const uint32_t a_kb  = (lane >> 4) << 4;
    // B (2 n-tiles per x4): lanes 0-7 n+0..7@k0; 8-15 n+0..7@k+8; 16-23 n+8..15@k0; 24-31 n+8..15@k+8
    const uint32_t b_row = wn + (lane & 7) + ((lane >> 4) << 3);
    const uint32_t b_kb  = ((lane >> 3) & 1) << 4;

    #pragma unroll
    for (int ks = 0; ks < 4; ks++) {
        const uint32_t kb = (uint32_t)(ks * 32);
        uint32_t bh[2][4], bl[2][4];
        #pragma unroll
        for (int nt2 = 0; nt2 < 2; nt2++) {
            uint32_t boff = sw128((b_row + nt2 * 16) * 128 + b_kb + kb);
            ldmx4(bh[nt2], sb + OFF_BH + boff);
            ldmx4(bl[nt2], sb + OFF_BL + boff);
        }
        #pragma unroll
        for (int mt = 0; mt < 4; mt++) {
            uint32_t aoff = sw128((a_row + mt * 16) * 128 + a_kb + kb);
            uint32_t ah[4], al[4];
            ldmx4(ah, sb + OFF_AH + aoff);
            ldmx4(al, sb + OFF_AL + aoff);
            #pragma unroll
            for (int nt = 0; nt < 4; nt++) {
                uint32_t b0h = bh[nt >> 1][(nt & 1) * 2];
                uint32_t b1h = bh[nt >> 1][(nt & 1) * 2 + 1];
                uint32_t b0l = bl[nt >> 1][(nt & 1) * 2];
                uint32_t b1l = bl[nt >> 1][(nt & 1) * 2 + 1];
                mma16816(acc[mt][nt], ah, b0h, b1h);
                mma16816(acc[mt][nt], ah, b0l, b1l);
                mma16816(acc[mt][nt], al, b0h, b1h);
            }
        }
    }

    // ---- Epilogue: bias + direct gmem stores (each quad writes a 32B sector) ----
    const float* bias_s = (const float*)(smem + OFF_BIAS);
    float* obase = out + ((size_t)bv * 4096u + (size_t)hp * 128u) * 1024u + e0;
    const int r0 = wm + (lane >> 2);           // +mt*16, +8 for c2/c3
    const int c0 = wn + ((lane & 3) << 1);     // +nt*8

    #pragma unroll
    for (int mt = 0; mt < 4; mt++) {
        #pragma unroll
        for (int nt = 0; nt < 4; nt++) {
            int col = c0 + nt * 8;
            float bx = bias_s[col], by = bias_s[col + 1];
            int row = r0 + mt * 16;
            float2 v0 = make_float2(acc[mt][nt][0] + bx, acc[mt][nt][1] + by);
            float2 v1 = make_float2(acc[mt][nt][2] + bx, acc[mt][nt][3] + by);
            *(float2*)(obase + (size_t)row * 1024u + col) = v0;
            *(float2*)(obase + (size_t)(row + 8) * 1024u + col) = v1;
        }
    }
}

extern "C" void kernel_launch(void* const* d_in, const int* in_sizes, int n_in,
                              void* d_out, int out_size) {
    const float* x    = (const float*)d_in[0];
    const int*   vars = (const int*)d_in[1];
    const float* pw   = (const float*)d_in[2];
    const float* pb   = (const float*)d_in[3];
    float*       out  = (float*)d_out;

    cudaFuncSetAttribute(patch_embed_mma,
                         cudaFuncAttributeMaxDynamicSharedMemorySize, SMEM_SZ);

    dim3 grid(8 /*E tiles*/, 32 /*patch-row pairs*/, 32 /*b*v*/);
    patch_embed_mma<<<grid, NTHREADS, SMEM_SZ>>>(x, vars, pw, pb, out);
}